// round 15
// baseline (speedup 1.0000x reference)
#include <cuda_runtime.h>
#include <cuda_bf16.h>
#include <math.h>
#include <cstdint>

// Problem constants
#define Bz   8
#define Lz   1025
#define Ez   384
#define Hz   6
#define Dz   64
#define PADz 16
#define Mz   (Bz * Lz)          // 8200 rows
#define SCALE 0.125f
#define WSZ  (Ez * Ez)          // 147456

// CLS split-K attention
#define CSPL  16
#define CKEYS 65                // ceil(1025/16)

// Scratch (device globals; no runtime allocation allowed)
__device__ float g_Q[Bz * Hz * Lz * Dz];
__device__ float g_K[Bz * Hz * Lz * Dz];
__device__ float g_V[Bz * Hz * Lz * Dz];
__device__ __nv_bfloat16 g_x_hi[Mz * Ez];
__device__ __nv_bfloat16 g_x_lo[Mz * Ez];
__device__ __nv_bfloat16 g_attn_hi[Mz * Ez];
__device__ __nv_bfloat16 g_attn_lo[Mz * Ez];
__device__ __nv_bfloat16 g_Wt_hi[4 * WSZ];   // transposed [z][n][k]
__device__ __nv_bfloat16 g_Wt_lo[4 * WSZ];
__device__ float g_cls_m[Bz * Hz * CSPL];
__device__ float g_cls_s[Bz * Hz * CSPL];
__device__ float g_cls_o[Bz * Hz * CSPL * Dz];
__device__ int   g_cls_cnt[Bz * Hz];

// ===========================================================================
// Helpers
// ===========================================================================
__device__ __forceinline__ uint32_t smem_u32(const void* p) {
    uint32_t a;
    asm("{ .reg .u64 t; cvta.to.shared.u64 t, %1; cvt.u32.u64 %0, t; }"
        : "=r"(a) : "l"(p));
    return a;
}

__device__ __forceinline__ void ldsm_x4(uint32_t (&r)[4], uint32_t saddr) {
    asm volatile("ldmatrix.sync.aligned.m8n8.x4.shared.b16 {%0,%1,%2,%3}, [%4];"
        : "=r"(r[0]), "=r"(r[1]), "=r"(r[2]), "=r"(r[3]) : "r"(saddr));
}

__device__ __forceinline__ void mma_bf16(float (&c)[4], const uint32_t (&a)[4],
                                         uint32_t b0, uint32_t b1) {
    asm volatile(
        "mma.sync.aligned.m16n8k16.row.col.f32.bf16.bf16.f32 "
        "{%0,%1,%2,%3}, {%4,%5,%6,%7}, {%8,%9}, {%0,%1,%2,%3};"
        : "+f"(c[0]), "+f"(c[1]), "+f"(c[2]), "+f"(c[3])
        : "r"(a[0]), "r"(a[1]), "r"(a[2]), "r"(a[3]), "r"(b0), "r"(b1));
}

__device__ __forceinline__ void cp_async16(uint32_t dst, const void* src, bool valid) {
    asm volatile("cp.async.ca.shared.global [%0], [%1], 16, %2;"
        :: "r"(dst), "l"(src), "r"(valid ? 16 : 0) : "memory");
}
#define CP_COMMIT() asm volatile("cp.async.commit_group;" ::: "memory")
template <int N>
__device__ __forceinline__ void cp_wait() {
    asm volatile("cp.async.wait_group %0;" :: "n"(N) : "memory");
}

__device__ __forceinline__ void split1(float x, __nv_bfloat16& h, __nv_bfloat16& l) {
    h = __float2bfloat16(x);
    l = __float2bfloat16(x - __bfloat162float(h));
}
__device__ __forceinline__ void split2(float x, float y, uint32_t& hi, uint32_t& lo) {
    __nv_bfloat16 hx, lx, hy, ly;
    split1(x, hx, lx);
    split1(y, hy, ly);
    hi = (uint32_t)__bfloat16_as_ushort(hx) | ((uint32_t)__bfloat16_as_ushort(hy) << 16);
    lo = (uint32_t)__bfloat16_as_ushort(lx) | ((uint32_t)__bfloat16_as_ushort(ly) << 16);
}

// ===========================================================================
// Fused prep: y==0 -> x conversion (+ counter reset); y in 1..4 -> weight z=y-1
// ===========================================================================
__global__ __launch_bounds__(256) void prep_kernel(
    const float* __restrict__ x,
    const float* __restrict__ Wq, const float* __restrict__ Wk,
    const float* __restrict__ Wv, const float* __restrict__ Wo)
{
    const int y = blockIdx.y;
    if (y == 0) {
        if (blockIdx.x == 0 && threadIdx.x < Bz * Hz)
            g_cls_cnt[threadIdx.x] = 0;
        int idx4 = blockIdx.x * 256 + threadIdx.x;
        int base = idx4 * 4;
        if (base >= Mz * Ez) return;
        float4 v = *(const float4*)(x + base);
        uint32_t h01, l01, h23, l23;
        split2(v.x, v.y, h01, l01);
        split2(v.z, v.w, h23, l23);
        *(uint2*)((char*)g_x_hi + (size_t)base * 2) = make_uint2(h01, h23);
        *(uint2*)((char*)g_x_lo + (size_t)base * 2) = make_uint2(l01, l23);
    } else {
        const int z = y - 1;
        const float* W = (z == 0) ? Wq : (z == 1) ? Wk : (z == 2) ? Wv : Wo;
        int idx = blockIdx.x * 256 + threadIdx.x;
        if (idx >= WSZ) return;
        int n = idx / Ez, k = idx - n * Ez;
        __nv_bfloat16 h, l;
        split1(W[(size_t)k * Ez + n], h, l);
        g_Wt_hi[(size_t)z * WSZ + idx] = h;
        g_Wt_lo[(size_t)z * WSZ + idx] = l;
    }
}

// ===========================================================================
// HMMA GEMMs: 3-stage cp.async pipeline, K-chunk 16 (24 chunks).
// QKV: CTA 128x128, warp 32x64 (4Mx2N), 2 CTAs/SM.
// OUT: CTA  64x128, warp 32x32 (2Mx4N), 3 CTAs/SM.
// KPAD=24 bf16/row -> 48B stride -> 8 ldsm rows hit distinct 16B slots.
// ===========================================================================
#define KP16 24

// --- QKV: stage = A(128x24x2B x2) + B(128x24x2B x2) = 24576 B ---
#define Q_A_HI 0
#define Q_A_LO 6144
#define Q_B_HI 12288
#define Q_B_LO 18432
#define Q_STG  24576

__global__ __launch_bounds__(256, 2) void qkv_gemm_kernel(
    const float* __restrict__ b0, const float* __restrict__ b1,
    const float* __restrict__ b2)
{
    extern __shared__ __align__(16) char smem[];
    const uint32_t sb = smem_u32(smem);

    const int tid  = threadIdx.x;
    const int wid  = tid >> 5;
    const int lane = tid & 31;
    const int bn = blockIdx.x;
    const int bm = blockIdx.y;
    const int z  = blockIdx.z;

    const __nv_bfloat16* Ah = g_x_hi;
    const __nv_bfloat16* Al = g_x_lo;
    const __nv_bfloat16* Bh = g_Wt_hi + (size_t)z * WSZ;
    const __nv_bfloat16* Bl = g_Wt_lo + (size_t)z * WSZ;
    const float* bias = (z == 0) ? b0 : (z == 1) ? b1 : b2;

    const int m0 = bm * 128;
    const int n0 = bn * 128;
    const int wm = wid & 3;
    const int wn = wid >> 2;

    float acc[2][8][4];
#pragma unroll
    for (int mt = 0; mt < 2; ++mt)
#pragma unroll
        for (int nt = 0; nt < 8; ++nt)
#pragma unroll
            for (int q = 0; q < 4; ++q) acc[mt][nt][q] = 0.f;

    const int srow = tid >> 1;             // 0..127
    const int scg  = (tid & 1) * 8;        // bf16 col of 16B granule

    auto stage = [&](int c, int s) {
        const uint32_t s0 = sb + s * Q_STG;
        const uint32_t soff = (uint32_t)(srow * KP16 + scg) * 2;
        const int ga = m0 + srow;
        const size_t aidx = (size_t)ga * Ez + c * 16 + scg;
        const bool av = (ga < Mz);
        cp_async16(s0 + Q_A_HI + soff, Ah + aidx, av);
        cp_async16(s0 + Q_A_LO + soff, Al + aidx, av);
        const size_t bidx = (size_t)(n0 + srow) * Ez + c * 16 + scg;
        cp_async16(s0 + Q_B_HI + soff, Bh + bidx, true);
        cp_async16(s0 + Q_B_LO + soff, Bl + bidx, true);
    };

    const int grp = lane >> 3;
    const int wl  = lane & 7;

    stage(0, 0); CP_COMMIT();
    stage(1, 1); CP_COMMIT();

    for (int c = 0; c < 24; ++c) {
        if (c < 23) cp_wait<1>(); else cp_wait<0>();
        __syncthreads();
        if (c + 2 < 24) {
            int s = c + 2; s -= (s >= 3) ? 3 : 0; s -= (s >= 3) ? 3 : 0;  // (c+2)%3 cheap
            stage(c + 2, (c + 2) % 3);
            CP_COMMIT();
        }

        const uint32_t s0 = sb + (c % 3) * Q_STG;

        uint32_t ah[2][4], al[2][4];
        const int a_r = wm * 32 + wl + (grp & 1) * 8;
        const int a_k = (grp >> 1) * 8;
#pragma unroll
        for (int mt = 0; mt < 2; ++mt) {
            uint32_t off = (uint32_t)((a_r + mt * 16) * KP16 + a_k) * 2;
            ldsm_x4(ah[mt], s0 + Q_A_HI + off);
            ldsm_x4(al[mt], s0 + Q_A_LO + off);
        }
        const int b_n = wn * 64 + wl + (grp >> 1) * 8;
        const int b_k = (grp & 1) * 8;
#pragma unroll
        for (int nt2 = 0; nt2 < 4; ++nt2) {
            uint32_t bh[4], bl[4];
            uint32_t off = (uint32_t)((b_n + nt2 * 16) * KP16 + b_k) * 2;
            ldsm_x4(bh, s0 + Q_B_HI + off);
            ldsm_x4(bl, s0 + Q_B_LO + off);
#pragma unroll
            for (int mt = 0; mt < 2; ++mt) {
                mma_bf16(acc[mt][nt2 * 2 + 0], ah[mt], bh[0], bh[1]);
                mma_bf16(acc[mt][nt2 * 2 + 0], ah[mt], bl[0], bl[1]);
                mma_bf16(acc[mt][nt2 * 2 + 0], al[mt], bh[0], bh[1]);
                mma_bf16(acc[mt][nt2 * 2 + 1], ah[mt], bh[2], bh[3]);
                mma_bf16(acc[mt][nt2 * 2 + 1], ah[mt], bl[2], bl[3]);
                mma_bf16(acc[mt][nt2 * 2 + 1], al[mt], bh[2], bh[3]);
            }
        }
    }

    const int tq = lane >> 2;
    const int tr = lane & 3;
#pragma unroll
    for (int mt = 0; mt < 2; ++mt) {
#pragma unroll
        for (int nt = 0; nt < 8; ++nt) {
            const int gcol = n0 + wn * 64 + nt * 8 + tr * 2;
            const float bv0 = bias[gcol];
            const float bv1 = bias[gcol + 1];
#pragma unroll
            for (int half = 0; half < 2; ++half) {
                const int grow = m0 + wm * 32 + mt * 16 + tq + half * 8;
                if (grow >= Mz) continue;
                float v0 = acc[mt][nt][half * 2 + 0] + bv0;
                float v1 = acc[mt][nt][half * 2 + 1] + bv1;
                int b = grow / Lz, l = grow - b * Lz;
                int h = gcol >> 6, d = gcol & 63;
                float* dst = (z == 0) ? g_Q : (z == 1) ? g_K : g_V;
                *(float2*)(dst + (((size_t)(b * Hz + h)) * Lz + l) * Dz + d) =
                    make_float2(v0, v1);
            }
        }
    }
}

// --- OUT: stage = A(64x24x2B x2) + B(128x24x2B x2) = 18432 B ---
#define O_A_HI 0
#define O_A_LO 3072
#define O_B_HI 6144
#define O_B_LO 12288
#define O_STG  18432

__global__ __launch_bounds__(256, 3) void out_gemm_kernel(
    const float* __restrict__ bias, float* __restrict__ Cout)
{
    extern __shared__ __align__(16) char smem[];
    const uint32_t sb = smem_u32(smem);

    const int tid  = threadIdx.x;
    const int wid  = tid >> 5;
    const int lane = tid & 31;
    const int bn = blockIdx.x;
    const int bm = blockIdx.y;

    const __nv_bfloat16* Ah = g_attn_hi;
    const __nv_bfloat16* Al = g_attn_lo;
    const __nv_bfloat16* Bh = g_Wt_hi + (size_t)3 * WSZ;
    const __nv_bfloat16* Bl = g_Wt_lo + (size_t)3 * WSZ;

    const int m0 = bm * 64;
    const int n0 = bn * 128;
    const int wm = wid & 1;
    const int wn = wid >> 1;

    float acc[2][4][4];
#pragma unroll
    for (int mt = 0; mt < 2; ++mt)
#pragma unroll
        for (int nt = 0; nt < 4; ++nt)
#pragma unroll
            for (int q = 0; q < 4; ++q) acc[mt][nt][q] = 0.f;

    const int srow = tid >> 1;             // 0..127
    const int scg  = (tid & 1) * 8;

    auto stage = [&](int c, int s) {
        const uint32_t s0 = sb + s * O_STG;
        const uint32_t soff = (uint32_t)(srow * KP16 + scg) * 2;
        if (tid < 128) {                   // A: 64 rows, rows = tid>>1
            const int ga = m0 + srow;
            const size_t aidx = (size_t)ga * Ez + c * 16 + scg;
            const bool av = (ga < Mz);
            cp_async16(s0 + O_A_HI + soff, Ah + aidx, av);
            cp_async16(s0 + O_A_LO + soff, Al + aidx, av);
        }
        const size_t bidx = (size_t)(n0 + srow) * Ez + c * 16 + scg;
        cp_async16(s0 + O_B_HI + soff, Bh + bidx, true);
        cp_async16(s0 + O_B_LO + soff, Bl + bidx, true);
    };

    const int grp = lane >> 3;
    const int wl  = lane & 7;

    stage(0, 0); CP_COMMIT();
    stage(1, 1); CP_COMMIT();

    for (int c = 0; c < 24; ++c) {
        if (c < 23) cp_wait<1>(); else cp_wait<0>();
        __syncthreads();
        if (c + 2 < 24) {
            stage(c + 2, (c + 2) % 3);
            CP_COMMIT();
        }

        const uint32_t s0 = sb + (c % 3) * O_STG;

        uint32_t ah[2][4], al[2][4];
        const int a_r = wm * 32 + wl + (grp & 1) * 8;
        const int a_k = (grp >> 1) * 8;
#pragma unroll
        for (int mt = 0; mt < 2; ++mt) {
            uint32_t off = (uint32_t)((a_r + mt * 16) * KP16 + a_k) * 2;
            ldsm_x4(ah[mt], s0 + O_A_HI + off);
            ldsm_x4(al[mt], s0 + O_A_LO + off);
        }
        const int b_n = wn * 32 + wl + (grp >> 1) * 8;
        const int b_k = (grp & 1) * 8;
#pragma unroll
        for (int nt2 = 0; nt2 < 2; ++nt2) {
            uint32_t bh[4], bl[4];
            uint32_t off = (uint32_t)((b_n + nt2 * 16) * KP16 + b_k) * 2;
            ldsm_x4(bh, s0 + O_B_HI + off);
            ldsm_x4(bl, s0 + O_B_LO + off);
#pragma unroll
            for (int mt = 0; mt < 2; ++mt) {
                mma_bf16(acc[mt][nt2 * 2 + 0], ah[mt], bh[0], bh[1]);
                mma_bf16(acc[mt][nt2 * 2 + 0], ah[mt], bl[0], bl[1]);
                mma_bf16(acc[mt][nt2 * 2 + 0], al[mt], bh[0], bh[1]);
                mma_bf16(acc[mt][nt2 * 2 + 1], ah[mt], bh[2], bh[3]);
                mma_bf16(acc[mt][nt2 * 2 + 1], ah[mt], bl[2], bl[3]);
                mma_bf16(acc[mt][nt2 * 2 + 1], al[mt], bh[2], bh[3]);
            }
        }
    }

    const int tq = lane >> 2;
    const int tr = lane & 3;
#pragma unroll
    for (int mt = 0; mt < 2; ++mt) {
#pragma unroll
        for (int nt = 0; nt < 4; ++nt) {
            const int gcol = n0 + wn * 32 + nt * 8 + tr * 2;
            const float bv0 = bias[gcol];
            const float bv1 = bias[gcol + 1];
#pragma unroll
            for (int half = 0; half < 2; ++half) {
                const int grow = m0 + wm * 32 + mt * 16 + tq + half * 8;
                if (grow >= Mz) continue;
                float v0 = acc[mt][nt][half * 2 + 0] + bv0;
                float v1 = acc[mt][nt][half * 2 + 1] + bv1;
                *(float2*)(Cout + (size_t)grow * Ez + gcol) = make_float2(v0, v1);
            }
        }
    }
}

// ===========================================================================
// Fused attention: grid (40, Hz, Bz) x 256 threads (unchanged from R12).
// ===========================================================================
#define KPADF 68

__global__ __launch_bounds__(256, 4) void attn_kernel()
{
    const int bx = blockIdx.x;
    const int h  = blockIdx.y;
    const int b  = blockIdx.z;
    const int tid = threadIdx.x;
    const unsigned FULL = 0xffffffffu;

    __shared__ float Ks[65][KPADF];
    __shared__ float Vs[65][64];
    __shared__ float Qs[32][64];
    __shared__ float ps[32][36];
    __shared__ float c_qv[2][Dz];
    __shared__ float c_sc[2][CKEYS];
    __shared__ float c_redm[2][4];
    __shared__ float c_reds[2][4];
    __shared__ float c_oacc[2][2][Dz];
    __shared__ int   s_last;

    const size_t bhbase = ((size_t)(b * Hz + h)) * Lz * Dz;

    if (bx < 32) {
        const int q0 = 1 + bx * 32;
        const float* Kbase = g_K + bhbase;
        const float* Vbase = g_V + bhbase;

        for (int i = tid; i < 65 * 16; i += 256) {
            int r = i >> 4;
            int c = (i & 15) * 4;
            int kidx = (r == 64) ? 0 : (q0 - 16 + r);
            float4 kv = make_float4(0.f, 0.f, 0.f, 0.f);
            float4 vv = kv;
            if (kidx >= 0 && kidx < Lz) {
                kv = *(const float4*)(Kbase + (size_t)kidx * Dz + c);
                vv = *(const float4*)(Vbase + (size_t)kidx * Dz + c);
            }
            *(float4*)&Ks[r][c] = kv;
            *(float4*)&Vs[r][c] = vv;
        }
        for (int i = tid; i < 32 * 16; i += 256) {
            int r = i >> 4;
            int c = (i & 15) * 4;
            *(float4*)&Qs[r][c] =
                *(const float4*)(g_Q + bhbase + (size_t)(q0 + r) * Dz + c);
        }
        __syncthreads();

        const int warp = tid >> 5;
        const int lane = tid & 31;
        const int base0 = warp * 4;

#pragma unroll
        for (int i = 0; i < 4; ++i) {
            const int ql = base0 + i;
            const int l  = q0 + ql;
            const int row = ql + lane;

            float s0 = 0.f, s1 = 0.f, s2 = 0.f, s3 = 0.f;
#pragma unroll
            for (int dg = 0; dg < 16; ++dg) {
                float4 q4 = *(const float4*)&Qs[ql][dg * 4];
                float4 k4 = *(const float4*)&Ks[row][dg * 4];
                s0 = fmaf(q4.x, k4.x, s0);
                s1 = fmaf(q4.y, k4.y, s1);
                s2 = fmaf(q4.z, k4.z, s2);
                s3 = fmaf(q4.w, k4.w, s3);
            }
            float sv = (s0 + s1) + (s2 + s3);

            float tv = 0.f;
            if (lane < 2) {
                const int row2 = (lane == 0) ? (ql + 32) : 64;
                float t0 = 0.f, t1 = 0.f, t2 = 0.f, t3 = 0.f;
#pragma unroll
                for (int dg = 0; dg < 16; ++dg) {
                    float4 q4  = *(const float4*)&Qs[ql][dg * 4];
                    float4 k24 = *(const float4*)&Ks[row2][dg * 4];
                    t0 = fmaf(q4.x, k24.x, t0);
                    t1 = fmaf(q4.y, k24.y, t1);
                    t2 = fmaf(q4.z, k24.z, t2);
                    t3 = fmaf(q4.w, k24.w, t3);
                }
                tv = (t0 + t1) + (t2 + t3);
            }

            const int kidx = l - PADz + lane;
            float s_lo = (kidx >= 1 && kidx < Lz) ? sv * SCALE : -INFINITY;
            float s_hi = -INFINITY;
            if (lane == 0) s_hi = (l + PADz < Lz) ? tv * SCALE : -INFINITY;
            if (lane == 1) s_hi = tv * SCALE;

            float m = fmaxf(s_lo, s_hi);
            m = fmaxf(m, __shfl_xor_sync(FULL, m, 16));
            m = fmaxf(m, __shfl_xor_sync(FULL, m, 8));
            m = fmaxf(m, __shfl_xor_sync(FULL, m, 4));
            m = fmaxf(m, __shfl_xor_sync(FULL, m, 2));
            m = fmaxf(m, __shfl_xor_sync(FULL, m, 1));

            float p  = __expf(s_lo - m);
            float ph = (lane < 2) ? __expf(s_hi - m) : 0.f;
            float t = p + ph;
            t += __shfl_xor_sync(FULL, t, 16);
            t += __shfl_xor_sync(FULL, t, 8);
            t += __shfl_xor_sync(FULL, t, 4);
            t += __shfl_xor_sync(FULL, t, 2);
            t += __shfl_xor_sync(FULL, t, 1);
            const float inv = 1.f / t;

            ps[ql][lane] = p * inv;
            if (lane < 2) ps[ql][32 + lane] = ph * inv;
        }
        __syncwarp();

        float a0[4] = {0.f, 0.f, 0.f, 0.f};
        float a1[4] = {0.f, 0.f, 0.f, 0.f};
#pragma unroll
        for (int j = 0; j < 36; ++j) {
            const float v0 = Vs[base0 + j][lane];
            const float v1 = Vs[base0 + j][lane + 32];
#pragma unroll
            for (int i = 0; i < 4; ++i) {
                const int w = j - i;
                if (w < 0 || w > 32) continue;
                const float pp = ps[base0 + i][w];
                a0[i] = fmaf(pp, v0, a0[i]);
                a1[i] = fmaf(pp, v1, a1[i]);
            }
        }
        {
            const float v0 = Vs[64][lane];
            const float v1 = Vs[64][lane + 32];
#pragma unroll
            for (int i = 0; i < 4; ++i) {
                const float pc = ps[base0 + i][33];
                a0[i] = fmaf(pc, v0, a0[i]);
                a1[i] = fmaf(pc, v1, a1[i]);
            }
        }

#pragma unroll
        for (int i = 0; i < 4; ++i) {
            const int l = q0 + base0 + i;
            __nv_bfloat16 h0, l0, h1, l1;
            split1(a0[i], h0, l0);
            split1(a1[i], h1, l1);
            size_t o = ((size_t)b * Lz + l) * Ez + h * Dz;
            g_attn_hi[o + lane]      = h0;
            g_attn_lo[o + lane]      = l0;
            g_attn_hi[o + lane + 32] = h1;
            g_attn_lo[o + lane + 32] = l1;
        }
        __syncthreads();
        __syncthreads();
        __syncthreads();
        __syncthreads();
        __syncthreads();
    } else {
        const int grpi = tid >> 7;
        const int gtid = tid & 127;
        const int warp = gtid >> 5;
        const int lane = tid & 31;
        const int sp = (bx - 32) * 2 + grpi;

        const int k0 = sp * CKEYS;
        const int nk = min(CKEYS, Lz - k0);

        if (gtid < Dz) c_qv[grpi][gtid] = g_Q[bhbase + gtid];
        __syncthreads();                                           // 1

        float lmax = -INFINITY;
        for (int i = warp; i < nk; i += 4) {
            const float* kr = g_K + bhbase + (size_t)(k0 + i) * Dz;
            float v = c_qv[grpi][lane] * kr[lane] + c_qv[grpi][lane + 32] * kr[lane + 32];
            v += __shfl_xor_sync(FULL, v, 16);
            v += __shfl_xor_sync(FULL, v, 8);
            v += __shfl_xor_sync(FULL, v, 4);
            v += __shfl_xor_sync(FULL, v, 2);
            v += __shfl_xor_sync(FULL, v, 1);
            v *= SCALE;
            if (lane == 0) c_sc[grpi][i] = v;
            lmax = fmaxf(lmax, v);
        }
        if (lane == 0) c_redm[grpi][warp] = lmax;
        __syncthreads();                                           // 2
        const float m = fmaxf(fmaxf(c_redm[grpi][0], c_redm[grpi][1]),
                              fmaxf(c_redm[grpi][2], c_redm[grpi][3]));

        float ls = 0.f;
        for (int i = gtid; i < nk; i += 128) {
            float p = __expf(c_sc[grpi][i] - m);
            c_sc[grpi][i] = p;
            ls += p;
        }
        ls += __shfl_xor_sync(FULL, ls, 16);
        ls += __shfl_xor_sync(FULL, ls, 8);
        ls += __shfl_xor_sync(FULL, ls, 4);
        ls += __shfl_xor_sync(FULL, ls, 2);
        ls += __shfl_xor_sync(FULL, ls, 1);
        if (lane == 0) c_reds[grpi][warp] = ls;
        __syncthreads();                                           // 3
        const float S = c_reds[grpi][0] + c_reds[grpi][1] +
                        c_reds[grpi][2] + c_reds[grpi][3];

        const int g = gtid >> 6;
        const int d = gtid & 63;
        float a = 0.f;
        for (int i = g; i < nk; i += 2)
            a = fmaf(c_sc[grpi][i], g_V[bhbase + (size_t)(k0 + i) * Dz + d], a);
        c_oacc[grpi][g][d] = a;
        __syncthreads();                                           // 4

        if (gtid < Dz) {
            const int idx = (b * Hz + h) * CSPL + sp;
            g_cls_o[(size_t)idx * Dz + gtid] = c_oacc[grpi][0][gtid] + c_oacc[grpi][1][gtid];
            if (gtid == 0) { g_cls_m[idx] = m; g_cls_s[idx] = S; }
        }

        __threadfence();
        __syncthreads();                                           // 5
        if (tid == 0) {
            int v = atomicAdd(&g_cls_cnt[b * Hz + h], 1);
            s_last = (v == 7);
        }
        __syncthreads();                                           // 6
        if (s_last && tid < Dz) {
            const int base = (b * Hz + h) * CSPL;
            float M = -INFINITY;
#pragma unroll
            for (int j = 0; j < CSPL; ++j) M = fmaxf(M, g_cls_m[base + j]);
            float Sg = 0.f, o = 0.f;
#pragma unroll
            for (int j = 0; j < CSPL; ++j) {
                float w = __expf(g_cls_m[base + j] - M);
                Sg = fmaf(g_cls_s[base + j], w, Sg);
                o  = fmaf(g_cls_o[(size_t)(base + j) * Dz + tid], w, o);
            }
            float acc = o / Sg;
            __nv_bfloat16 hh, ll;
            split1(acc, hh, ll);
            size_t off = ((size_t)b * Lz) * Ez + h * Dz + tid;
            g_attn_hi[off] = hh;
            g_attn_lo[off] = ll;
        }
    }
}

// ---------------------------------------------------------------------------
// Launch
// ---------------------------------------------------------------------------
extern "C" void kernel_launch(void* const* d_in, const int* in_sizes, int n_in,
                              void* d_out, int out_size)
{
    const float* x  = (const float*)d_in[0];
    const float* Wq = (const float*)d_in[1];
    const float* bq = (const float*)d_in[2];
    const float* Wk = (const float*)d_in[3];
    const float* bk = (const float*)d_in[4];
    const float* Wv = (const float*)d_in[5];
    const float* bv = (const float*)d_in[6];
    const float* Wo = (const float*)d_in[7];
    const float* bo = (const float*)d_in[8];
    float* out = (float*)d_out;

    static bool attr_done = false;
    if (!attr_done) {
        cudaFuncSetAttribute((const void*)qkv_gemm_kernel,
                             cudaFuncAttributeMaxDynamicSharedMemorySize, 3 * Q_STG);
        cudaFuncSetAttribute((const void*)out_gemm_kernel,
                             cudaFuncAttributeMaxDynamicSharedMemorySize, 3 * O_STG);
        attr_done = true;
    }

    prep_kernel<<<dim3((Mz * Ez / 4 + 255) / 256, 5), 256>>>(x, Wq, Wk, Wv, Wo);

    dim3 gridQKV(Ez / 128, (Mz + 127) / 128, 3);   // (3, 65, 3) = 585 CTAs
    dim3 gridO(Ez / 128, (Mz + 63) / 64);          // (3, 129)   = 387 CTAs

    qkv_gemm_kernel<<<gridQKV, 256, 3 * Q_STG>>>(bq, bk, bv);

    attn_kernel<<<dim3(40, Hz, Bz), 256>>>();      // window + CLS + combine

    out_gemm_kernel<<<gridO, 256, 3 * O_STG>>>(bo, out);
}

// round 16
// speedup vs baseline: 1.1070x; 1.1070x over previous
#include <cuda_runtime.h>
#include <cuda_bf16.h>
#include <math.h>
#include <cstdint>

// Problem constants
#define Bz   8
#define Lz   1025
#define Ez   384
#define Hz   6
#define Dz   64
#define PADz 16
#define Mz   (Bz * Lz)          // 8200 rows
#define SCALE 0.125f
#define WSZ  (Ez * Ez)          // 147456

// CLS split-K attention
#define CSPL  16
#define CKEYS 65                // ceil(1025/16)

// Scratch (device globals; no runtime allocation allowed)
__device__ float g_Q[Bz * Hz * Lz * Dz];
__device__ float g_K[Bz * Hz * Lz * Dz];
__device__ float g_V[Bz * Hz * Lz * Dz];
__device__ __nv_bfloat16 g_x_hi[Mz * Ez];
__device__ __nv_bfloat16 g_x_lo[Mz * Ez];
__device__ __nv_bfloat16 g_attn_hi[Mz * Ez];
__device__ __nv_bfloat16 g_attn_lo[Mz * Ez];
__device__ __nv_bfloat16 g_Wt_hi[4 * WSZ];   // transposed [z][n][k]
__device__ __nv_bfloat16 g_Wt_lo[4 * WSZ];
__device__ float g_cls_m[Bz * Hz * CSPL];
__device__ float g_cls_s[Bz * Hz * CSPL];
__device__ float g_cls_o[Bz * Hz * CSPL * Dz];
__device__ int   g_cls_cnt[Bz * Hz];

// ===========================================================================
// Helpers
// ===========================================================================
__device__ __forceinline__ uint32_t smem_u32(const void* p) {
    uint32_t a;
    asm("{ .reg .u64 t; cvta.to.shared.u64 t, %1; cvt.u32.u64 %0, t; }"
        : "=r"(a) : "l"(p));
    return a;
}

__device__ __forceinline__ void ldsm_x4(uint32_t (&r)[4], uint32_t saddr) {
    asm volatile("ldmatrix.sync.aligned.m8n8.x4.shared.b16 {%0,%1,%2,%3}, [%4];"
        : "=r"(r[0]), "=r"(r[1]), "=r"(r[2]), "=r"(r[3]) : "r"(saddr));
}

__device__ __forceinline__ void mma_bf16(float (&c)[4], const uint32_t (&a)[4],
                                         uint32_t b0, uint32_t b1) {
    asm volatile(
        "mma.sync.aligned.m16n8k16.row.col.f32.bf16.bf16.f32 "
        "{%0,%1,%2,%3}, {%4,%5,%6,%7}, {%8,%9}, {%0,%1,%2,%3};"
        : "+f"(c[0]), "+f"(c[1]), "+f"(c[2]), "+f"(c[3])
        : "r"(a[0]), "r"(a[1]), "r"(a[2]), "r"(a[3]), "r"(b0), "r"(b1));
}

__device__ __forceinline__ void cp_async16(uint32_t dst, const void* src, bool valid) {
    asm volatile("cp.async.ca.shared.global [%0], [%1], 16, %2;"
        :: "r"(dst), "l"(src), "r"(valid ? 16 : 0) : "memory");
}
#define CP_COMMIT() asm volatile("cp.async.commit_group;" ::: "memory")
template <int N>
__device__ __forceinline__ void cp_wait() {
    asm volatile("cp.async.wait_group %0;" :: "n"(N) : "memory");
}

__device__ __forceinline__ void split1(float x, __nv_bfloat16& h, __nv_bfloat16& l) {
    h = __float2bfloat16(x);
    l = __float2bfloat16(x - __bfloat162float(h));
}
__device__ __forceinline__ void split2(float x, float y, uint32_t& hi, uint32_t& lo) {
    __nv_bfloat16 hx, lx, hy, ly;
    split1(x, hx, lx);
    split1(y, hy, ly);
    hi = (uint32_t)__bfloat16_as_ushort(hx) | ((uint32_t)__bfloat16_as_ushort(hy) << 16);
    lo = (uint32_t)__bfloat16_as_ushort(lx) | ((uint32_t)__bfloat16_as_ushort(ly) << 16);
}

// ===========================================================================
// Fused prep: y==0 -> x conversion (+ counter reset); y in 1..4 -> weight z=y-1
// ===========================================================================
__global__ __launch_bounds__(256) void prep_kernel(
    const float* __restrict__ x,
    const float* __restrict__ Wq, const float* __restrict__ Wk,
    const float* __restrict__ Wv, const float* __restrict__ Wo)
{
    const int y = blockIdx.y;
    if (y == 0) {
        if (blockIdx.x == 0 && threadIdx.x < Bz * Hz)
            g_cls_cnt[threadIdx.x] = 0;
        int idx4 = blockIdx.x * 256 + threadIdx.x;
        int base = idx4 * 4;
        if (base >= Mz * Ez) return;
        float4 v = *(const float4*)(x + base);
        uint32_t h01, l01, h23, l23;
        split2(v.x, v.y, h01, l01);
        split2(v.z, v.w, h23, l23);
        *(uint2*)((char*)g_x_hi + (size_t)base * 2) = make_uint2(h01, h23);
        *(uint2*)((char*)g_x_lo + (size_t)base * 2) = make_uint2(l01, l23);
    } else {
        const int z = y - 1;
        const float* W = (z == 0) ? Wq : (z == 1) ? Wk : (z == 2) ? Wv : Wo;
        int idx = blockIdx.x * 256 + threadIdx.x;
        if (idx >= WSZ) return;
        int n = idx / Ez, k = idx - n * Ez;
        __nv_bfloat16 h, l;
        split1(W[(size_t)k * Ez + n], h, l);
        g_Wt_hi[(size_t)z * WSZ + idx] = h;
        g_Wt_lo[(size_t)z * WSZ + idx] = l;
    }
}

// ===========================================================================
// HMMA GEMMs: K-chunk 32, 2-stage cp.async pipeline, one sync per chunk.
// QKV: CTA 128x128, warp 32x64 (4Mx2N), 2 CTAs/SM.  (R14 measured optimum)
// OUT: CTA  64x128, warp 32x32 (2Mx4N), 3 CTAs/SM.  (R14 measured optimum)
// ===========================================================================
#define KPAD 40

// --- 128x128 variant (QKV) ---
#define Q_ARR_B 10240
#define Q_STG_B 40960

__global__ __launch_bounds__(256, 2) void qkv_gemm_kernel(
    const float* __restrict__ b0, const float* __restrict__ b1,
    const float* __restrict__ b2)
{
    extern __shared__ __align__(16) char smem[];
    const uint32_t sb = smem_u32(smem);

    const int tid  = threadIdx.x;
    const int wid  = tid >> 5;
    const int lane = tid & 31;
    const int bn = blockIdx.x;
    const int bm = blockIdx.y;
    const int z  = blockIdx.z;

    const __nv_bfloat16* Ah = g_x_hi;
    const __nv_bfloat16* Al = g_x_lo;
    const __nv_bfloat16* Bh = g_Wt_hi + (size_t)z * WSZ;
    const __nv_bfloat16* Bl = g_Wt_lo + (size_t)z * WSZ;
    const float* bias = (z == 0) ? b0 : (z == 1) ? b1 : b2;

    const int m0 = bm * 128;
    const int n0 = bn * 128;
    const int wm = wid & 3;
    const int wn = wid >> 2;

    float acc[2][8][4];
#pragma unroll
    for (int mt = 0; mt < 2; ++mt)
#pragma unroll
        for (int nt = 0; nt < 8; ++nt)
#pragma unroll
            for (int q = 0; q < 4; ++q) acc[mt][nt][q] = 0.f;

    const int srow0 = tid >> 2;
    const int scol  = (tid & 3) * 8;

    auto stage = [&](int c, int s) {
        const uint32_t s0 = sb + s * Q_STG_B;
#pragma unroll
        for (int t = 0; t < 2; ++t) {
            const int row = srow0 + t * 64;
            const uint32_t soff = (uint32_t)(row * KPAD + scol) * 2;
            const int ga = m0 + row;
            const size_t aidx = (size_t)ga * Ez + c * 32 + scol;
            const bool av = (ga < Mz);
            cp_async16(s0 + 0 * Q_ARR_B + soff, Ah + aidx, av);
            cp_async16(s0 + 1 * Q_ARR_B + soff, Al + aidx, av);
            const size_t bidx = (size_t)(n0 + row) * Ez + c * 32 + scol;
            cp_async16(s0 + 2 * Q_ARR_B + soff, Bh + bidx, true);
            cp_async16(s0 + 3 * Q_ARR_B + soff, Bl + bidx, true);
        }
    };

    const int grp = lane >> 3;
    const int wl  = lane & 7;

    stage(0, 0);
    CP_COMMIT();

    for (int c = 0; c < 12; ++c) {
        cp_wait<0>();
        __syncthreads();
        if (c < 11) {
            stage(c + 1, (c + 1) & 1);
            CP_COMMIT();
        }

        const uint32_t s0 = sb + (c & 1) * Q_STG_B;
        const uint32_t sA_hi = s0;
        const uint32_t sA_lo = s0 + Q_ARR_B;
        const uint32_t sB_hi = s0 + 2 * Q_ARR_B;
        const uint32_t sB_lo = s0 + 3 * Q_ARR_B;

#pragma unroll
        for (int ks = 0; ks < 2; ++ks) {
            const int k0 = ks * 16;
            uint32_t ah[2][4], al[2][4];
            const int a_r = wm * 32 + wl + (grp & 1) * 8;
            const int a_k = k0 + (grp >> 1) * 8;
#pragma unroll
            for (int mt = 0; mt < 2; ++mt) {
                uint32_t off = (uint32_t)((a_r + mt * 16) * KPAD + a_k) * 2;
                ldsm_x4(ah[mt], sA_hi + off);
                ldsm_x4(al[mt], sA_lo + off);
            }
            const int b_n = wn * 64 + wl + (grp >> 1) * 8;
            const int b_k = k0 + (grp & 1) * 8;
#pragma unroll
            for (int nt2 = 0; nt2 < 4; ++nt2) {
                uint32_t bh[4], bl[4];
                uint32_t off = (uint32_t)((b_n + nt2 * 16) * KPAD + b_k) * 2;
                ldsm_x4(bh, sB_hi + off);
                ldsm_x4(bl, sB_lo + off);
#pragma unroll
                for (int mt = 0; mt < 2; ++mt) {
                    mma_bf16(acc[mt][nt2 * 2 + 0], ah[mt], bh[0], bh[1]);
                    mma_bf16(acc[mt][nt2 * 2 + 0], ah[mt], bl[0], bl[1]);
                    mma_bf16(acc[mt][nt2 * 2 + 0], al[mt], bh[0], bh[1]);
                    mma_bf16(acc[mt][nt2 * 2 + 1], ah[mt], bh[2], bh[3]);
                    mma_bf16(acc[mt][nt2 * 2 + 1], ah[mt], bl[2], bl[3]);
                    mma_bf16(acc[mt][nt2 * 2 + 1], al[mt], bh[2], bh[3]);
                }
            }
        }
    }

    const int tq = lane >> 2;
    const int tr = lane & 3;
#pragma unroll
    for (int mt = 0; mt < 2; ++mt) {
#pragma unroll
        for (int nt = 0; nt < 8; ++nt) {
            const int gcol = n0 + wn * 64 + nt * 8 + tr * 2;
            const float bv0 = bias[gcol];
            const float bv1 = bias[gcol + 1];
#pragma unroll
            for (int half = 0; half < 2; ++half) {
                const int grow = m0 + wm * 32 + mt * 16 + tq + half * 8;
                if (grow >= Mz) continue;
                float v0 = acc[mt][nt][half * 2 + 0] + bv0;
                float v1 = acc[mt][nt][half * 2 + 1] + bv1;
                int b = grow / Lz, l = grow - b * Lz;
                int h = gcol >> 6, d = gcol & 63;
                float* dst = (z == 0) ? g_Q : (z == 1) ? g_K : g_V;
                *(float2*)(dst + (((size_t)(b * Hz + h)) * Lz + l) * Dz + d) =
                    make_float2(v0, v1);
            }
        }
    }
}

// --- 64x128 variant (OUT) ---
#define O_SA_HI  0
#define O_SA_LO  5120
#define O_SB_HI  10240
#define O_SB_LO  20480
#define O_STG_B  30720

__global__ __launch_bounds__(256, 3) void out_gemm_kernel(
    const float* __restrict__ bias, float* __restrict__ Cout)
{
    extern __shared__ __align__(16) char smem[];
    const uint32_t sb = smem_u32(smem);

    const int tid  = threadIdx.x;
    const int wid  = tid >> 5;
    const int lane = tid & 31;
    const int bn = blockIdx.x;
    const int bm = blockIdx.y;

    const __nv_bfloat16* Ah = g_attn_hi;
    const __nv_bfloat16* Al = g_attn_lo;
    const __nv_bfloat16* Bh = g_Wt_hi + (size_t)3 * WSZ;
    const __nv_bfloat16* Bl = g_Wt_lo + (size_t)3 * WSZ;

    const int m0 = bm * 64;
    const int n0 = bn * 128;
    const int wm = wid & 1;
    const int wn = wid >> 1;

    float acc[2][4][4];
#pragma unroll
    for (int mt = 0; mt < 2; ++mt)
#pragma unroll
        for (int nt = 0; nt < 4; ++nt)
#pragma unroll
            for (int q = 0; q < 4; ++q) acc[mt][nt][q] = 0.f;

    const int srow = tid >> 2;
    const int scg  = (tid & 3) * 8;

    auto stage = [&](int c, int s) {
        const uint32_t s0 = sb + s * O_STG_B;
        {
            const uint32_t soff = (uint32_t)(srow * KPAD + scg) * 2;
            const int ga = m0 + srow;
            const size_t aidx = (size_t)ga * Ez + c * 32 + scg;
            const bool av = (ga < Mz);
            cp_async16(s0 + O_SA_HI + soff, Ah + aidx, av);
            cp_async16(s0 + O_SA_LO + soff, Al + aidx, av);
        }
#pragma unroll
        for (int t = 0; t < 2; ++t) {
            const int row = srow + t * 64;
            const uint32_t soff = (uint32_t)(row * KPAD + scg) * 2;
            const size_t bidx = (size_t)(n0 + row) * Ez + c * 32 + scg;
            cp_async16(s0 + O_SB_HI + soff, Bh + bidx, true);
            cp_async16(s0 + O_SB_LO + soff, Bl + bidx, true);
        }
    };

    const int grp = lane >> 3;
    const int wl  = lane & 7;

    stage(0, 0);
    CP_COMMIT();

    for (int c = 0; c < 12; ++c) {
        cp_wait<0>();
        __syncthreads();
        if (c < 11) {
            stage(c + 1, (c + 1) & 1);
            CP_COMMIT();
        }

        const uint32_t s0 = sb + (c & 1) * O_STG_B;

#pragma unroll
        for (int ks = 0; ks < 2; ++ks) {
            const int k0 = ks * 16;
            uint32_t ah[2][4], al[2][4];
            const int a_r = wm * 32 + wl + (grp & 1) * 8;
            const int a_k = k0 + (grp >> 1) * 8;
#pragma unroll
            for (int mt = 0; mt < 2; ++mt) {
                uint32_t off = (uint32_t)((a_r + mt * 16) * KPAD + a_k) * 2;
                ldsm_x4(ah[mt], s0 + O_SA_HI + off);
                ldsm_x4(al[mt], s0 + O_SA_LO + off);
            }
            const int b_n = wn * 32 + wl + (grp >> 1) * 8;
            const int b_k = k0 + (grp & 1) * 8;
#pragma unroll
            for (int nt2 = 0; nt2 < 2; ++nt2) {
                uint32_t bh[4], bl[4];
                uint32_t off = (uint32_t)((b_n + nt2 * 16) * KPAD + b_k) * 2;
                ldsm_x4(bh, s0 + O_SB_HI + off);
                ldsm_x4(bl, s0 + O_SB_LO + off);
#pragma unroll
                for (int mt = 0; mt < 2; ++mt) {
                    mma_bf16(acc[mt][nt2 * 2 + 0], ah[mt], bh[0], bh[1]);
                    mma_bf16(acc[mt][nt2 * 2 + 0], ah[mt], bl[0], bl[1]);
                    mma_bf16(acc[mt][nt2 * 2 + 0], al[mt], bh[0], bh[1]);
                    mma_bf16(acc[mt][nt2 * 2 + 1], ah[mt], bh[2], bh[3]);
                    mma_bf16(acc[mt][nt2 * 2 + 1], ah[mt], bl[2], bl[3]);
                    mma_bf16(acc[mt][nt2 * 2 + 1], al[mt], bh[2], bh[3]);
                }
            }
        }
    }

    const int tq = lane >> 2;
    const int tr = lane & 3;
#pragma unroll
    for (int mt = 0; mt < 2; ++mt) {
#pragma unroll
        for (int nt = 0; nt < 4; ++nt) {
            const int gcol = n0 + wn * 32 + nt * 8 + tr * 2;
            const float bv0 = bias[gcol];
            const float bv1 = bias[gcol + 1];
#pragma unroll
            for (int half = 0; half < 2; ++half) {
                const int grow = m0 + wm * 32 + mt * 16 + tq + half * 8;
                if (grow >= Mz) continue;
                float v0 = acc[mt][nt][half * 2 + 0] + bv0;
                float v1 = acc[mt][nt][half * 2 + 1] + bv1;
                *(float2*)(Cout + (size_t)grow * Ez + gcol) = make_float2(v0, v1);
            }
        }
    }
}

// ===========================================================================
// Fused attention: grid (40, Hz, Bz) x 256 threads.
//   bx in [0,32): windowed attention
//   bx in [32,40): CLS split-K partials; LAST CTA per (b,h) also combines.
// (bar.sync is CTA-scoped; no cross-path barrier padding needed.)
// ===========================================================================
#define KPADF 68

__global__ __launch_bounds__(256, 4) void attn_kernel()
{
    const int bx = blockIdx.x;
    const int h  = blockIdx.y;
    const int b  = blockIdx.z;
    const int tid = threadIdx.x;
    const unsigned FULL = 0xffffffffu;

    __shared__ float Ks[65][KPADF];
    __shared__ float Vs[65][64];
    __shared__ float Qs[32][64];
    __shared__ float ps[32][36];
    __shared__ float c_qv[2][Dz];
    __shared__ float c_sc[2][CKEYS];
    __shared__ float c_redm[2][4];
    __shared__ float c_reds[2][4];
    __shared__ float c_oacc[2][2][Dz];
    __shared__ int   s_last;

    const size_t bhbase = ((size_t)(b * Hz + h)) * Lz * Dz;

    if (bx < 32) {
        const int q0 = 1 + bx * 32;
        const float* Kbase = g_K + bhbase;
        const float* Vbase = g_V + bhbase;

        for (int i = tid; i < 65 * 16; i += 256) {
            int r = i >> 4;
            int c = (i & 15) * 4;
            int kidx = (r == 64) ? 0 : (q0 - 16 + r);
            float4 kv = make_float4(0.f, 0.f, 0.f, 0.f);
            float4 vv = kv;
            if (kidx >= 0 && kidx < Lz) {
                kv = *(const float4*)(Kbase + (size_t)kidx * Dz + c);
                vv = *(const float4*)(Vbase + (size_t)kidx * Dz + c);
            }
            *(float4*)&Ks[r][c] = kv;
            *(float4*)&Vs[r][c] = vv;
        }
        for (int i = tid; i < 32 * 16; i += 256) {
            int r = i >> 4;
            int c = (i & 15) * 4;
            *(float4*)&Qs[r][c] =
                *(const float4*)(g_Q + bhbase + (size_t)(q0 + r) * Dz + c);
        }
        __syncthreads();

        const int warp = tid >> 5;
        const int lane = tid & 31;
        const int base0 = warp * 4;

#pragma unroll
        for (int i = 0; i < 4; ++i) {
            const int ql = base0 + i;
            const int l  = q0 + ql;
            const int row = ql + lane;

            float s0 = 0.f, s1 = 0.f, s2 = 0.f, s3 = 0.f;
#pragma unroll
            for (int dg = 0; dg < 16; ++dg) {
                float4 q4 = *(const float4*)&Qs[ql][dg * 4];
                float4 k4 = *(const float4*)&Ks[row][dg * 4];
                s0 = fmaf(q4.x, k4.x, s0);
                s1 = fmaf(q4.y, k4.y, s1);
                s2 = fmaf(q4.z, k4.z, s2);
                s3 = fmaf(q4.w, k4.w, s3);
            }
            float sv = (s0 + s1) + (s2 + s3);

            float tv = 0.f;
            if (lane < 2) {
                const int row2 = (lane == 0) ? (ql + 32) : 64;
                float t0 = 0.f, t1 = 0.f, t2 = 0.f, t3 = 0.f;
#pragma unroll
                for (int dg = 0; dg < 16; ++dg) {
                    float4 q4  = *(const float4*)&Qs[ql][dg * 4];
                    float4 k24 = *(const float4*)&Ks[row2][dg * 4];
                    t0 = fmaf(q4.x, k24.x, t0);
                    t1 = fmaf(q4.y, k24.y, t1);
                    t2 = fmaf(q4.z, k24.z, t2);
                    t3 = fmaf(q4.w, k24.w, t3);
                }
                tv = (t0 + t1) + (t2 + t3);
            }

            const int kidx = l - PADz + lane;
            float s_lo = (kidx >= 1 && kidx < Lz) ? sv * SCALE : -INFINITY;
            float s_hi = -INFINITY;
            if (lane == 0) s_hi = (l + PADz < Lz) ? tv * SCALE : -INFINITY;
            if (lane == 1) s_hi = tv * SCALE;

            float m = fmaxf(s_lo, s_hi);
            m = fmaxf(m, __shfl_xor_sync(FULL, m, 16));
            m = fmaxf(m, __shfl_xor_sync(FULL, m, 8));
            m = fmaxf(m, __shfl_xor_sync(FULL, m, 4));
            m = fmaxf(m, __shfl_xor_sync(FULL, m, 2));
            m = fmaxf(m, __shfl_xor_sync(FULL, m, 1));

            float p  = __expf(s_lo - m);
            float ph = (lane < 2) ? __expf(s_hi - m) : 0.f;
            float t = p + ph;
            t += __shfl_xor_sync(FULL, t, 16);
            t += __shfl_xor_sync(FULL, t, 8);
            t += __shfl_xor_sync(FULL, t, 4);
            t += __shfl_xor_sync(FULL, t, 2);
            t += __shfl_xor_sync(FULL, t, 1);
            const float inv = 1.f / t;

            ps[ql][lane] = p * inv;
            if (lane < 2) ps[ql][32 + lane] = ph * inv;
        }
        __syncwarp();

        float a0[4] = {0.f, 0.f, 0.f, 0.f};
        float a1[4] = {0.f, 0.f, 0.f, 0.f};
#pragma unroll
        for (int j = 0; j < 36; ++j) {
            const float v0 = Vs[base0 + j][lane];
            const float v1 = Vs[base0 + j][lane + 32];
#pragma unroll
            for (int i = 0; i < 4; ++i) {
                const int w = j - i;
                if (w < 0 || w > 32) continue;
                const float pp = ps[base0 + i][w];
                a0[i] = fmaf(pp, v0, a0[i]);
                a1[i] = fmaf(pp, v1, a1[i]);
            }
        }
        {
            const float v0 = Vs[64][lane];
            const float v1 = Vs[64][lane + 32];
#pragma unroll
            for (int i = 0; i < 4; ++i) {
                const float pc = ps[base0 + i][33];
                a0[i] = fmaf(pc, v0, a0[i]);
                a1[i] = fmaf(pc, v1, a1[i]);
            }
        }

#pragma unroll
        for (int i = 0; i < 4; ++i) {
            const int l = q0 + base0 + i;
            __nv_bfloat16 h0, l0, h1, l1;
            split1(a0[i], h0, l0);
            split1(a1[i], h1, l1);
            size_t o = ((size_t)b * Lz + l) * Ez + h * Dz;
            g_attn_hi[o + lane]      = h0;
            g_attn_lo[o + lane]      = l0;
            g_attn_hi[o + lane + 32] = h1;
            g_attn_lo[o + lane + 32] = l1;
        }
    } else {
        const int grpi = tid >> 7;
        const int gtid = tid & 127;
        const int warp = gtid >> 5;
        const int lane = tid & 31;
        const int sp = (bx - 32) * 2 + grpi;

        const int k0 = sp * CKEYS;
        const int nk = min(CKEYS, Lz - k0);

        if (gtid < Dz) c_qv[grpi][gtid] = g_Q[bhbase + gtid];
        __syncthreads();

        float lmax = -INFINITY;
        for (int i = warp; i < nk; i += 4) {
            const float* kr = g_K + bhbase + (size_t)(k0 + i) * Dz;
            float v = c_qv[grpi][lane] * kr[lane] + c_qv[grpi][lane + 32] * kr[lane + 32];
            v += __shfl_xor_sync(FULL, v, 16);
            v += __shfl_xor_sync(FULL, v, 8);
            v += __shfl_xor_sync(FULL, v, 4);
            v += __shfl_xor_sync(FULL, v, 2);
            v += __shfl_xor_sync(FULL, v, 1);
            v *= SCALE;
            if (lane == 0) c_sc[grpi][i] = v;
            lmax = fmaxf(lmax, v);
        }
        if (lane == 0) c_redm[grpi][warp] = lmax;
        __syncthreads();
        const float m = fmaxf(fmaxf(c_redm[grpi][0], c_redm[grpi][1]),
                              fmaxf(c_redm[grpi][2], c_redm[grpi][3]));

        float ls = 0.f;
        for (int i = gtid; i < nk; i += 128) {
            float p = __expf(c_sc[grpi][i] - m);
            c_sc[grpi][i] = p;
            ls += p;
        }
        ls += __shfl_xor_sync(FULL, ls, 16);
        ls += __shfl_xor_sync(FULL, ls, 8);
        ls += __shfl_xor_sync(FULL, ls, 4);
        ls += __shfl_xor_sync(FULL, ls, 2);
        ls += __shfl_xor_sync(FULL, ls, 1);
        if (lane == 0) c_reds[grpi][warp] = ls;
        __syncthreads();
        const float S = c_reds[grpi][0] + c_reds[grpi][1] +
                        c_reds[grpi][2] + c_reds[grpi][3];

        const int g = gtid >> 6;
        const int d = gtid & 63;
        float a = 0.f;
        for (int i = g; i < nk; i += 2)
            a = fmaf(c_sc[grpi][i], g_V[bhbase + (size_t)(k0 + i) * Dz + d], a);
        c_oacc[grpi][g][d] = a;
        __syncthreads();

        if (gtid < Dz) {
            const int idx = (b * Hz + h) * CSPL + sp;
            g_cls_o[(size_t)idx * Dz + gtid] = c_oacc[grpi][0][gtid] + c_oacc[grpi][1][gtid];
            if (gtid == 0) { g_cls_m[idx] = m; g_cls_s[idx] = S; }
        }

        __threadfence();
        __syncthreads();
        if (tid == 0) {
            int v = atomicAdd(&g_cls_cnt[b * Hz + h], 1);
            s_last = (v == 7);
        }
        __syncthreads();
        if (s_last && tid < Dz) {
            const int base = (b * Hz + h) * CSPL;
            float M = -INFINITY;
#pragma unroll
            for (int j = 0; j < CSPL; ++j) M = fmaxf(M, g_cls_m[base + j]);
            float Sg = 0.f, o = 0.f;
#pragma unroll
            for (int j = 0; j < CSPL; ++j) {
                float w = __expf(g_cls_m[base + j] - M);
                Sg = fmaf(g_cls_s[base + j], w, Sg);
                o  = fmaf(g_cls_o[(size_t)(base + j) * Dz + tid], w, o);
            }
            float acc = o / Sg;
            __nv_bfloat16 hh, ll;
            split1(acc, hh, ll);
            size_t off = ((size_t)b * Lz) * Ez + h * Dz + tid;
            g_attn_hi[off] = hh;
            g_attn_lo[off] = ll;
        }
    }
}

// ---------------------------------------------------------------------------
// Launch
// ---------------------------------------------------------------------------
extern "C" void kernel_launch(void* const* d_in, const int* in_sizes, int n_in,
                              void* d_out, int out_size)
{
    const float* x  = (const float*)d_in[0];
    const float* Wq = (const float*)d_in[1];
    const float* bq = (const float*)d_in[2];
    const float* Wk = (const float*)d_in[3];
    const float* bk = (const float*)d_in[4];
    const float* Wv = (const float*)d_in[5];
    const float* bv = (const float*)d_in[6];
    const float* Wo = (const float*)d_in[7];
    const float* bo = (const float*)d_in[8];
    float* out = (float*)d_out;

    static bool attr_done = false;
    if (!attr_done) {
        cudaFuncSetAttribute((const void*)qkv_gemm_kernel,
                             cudaFuncAttributeMaxDynamicSharedMemorySize, 2 * Q_STG_B);
        cudaFuncSetAttribute((const void*)out_gemm_kernel,
                             cudaFuncAttributeMaxDynamicSharedMemorySize, 2 * O_STG_B);
        attr_done = true;
    }

    prep_kernel<<<dim3((Mz * Ez / 4 + 255) / 256, 5), 256>>>(x, Wq, Wk, Wv, Wo);

    dim3 gridQKV(Ez / 128, (Mz + 127) / 128, 3);   // (3, 65, 3) = 585 CTAs
    dim3 gridO(Ez / 128, (Mz + 63) / 64);          // (3, 129)   = 387 CTAs

    qkv_gemm_kernel<<<gridQKV, 256, 2 * Q_STG_B>>>(bq, bk, bv);

    attn_kernel<<<dim3(40, Hz, Bz), 256>>>();      // window + CLS + combine

    out_gemm_kernel<<<gridO, 256, 2 * O_STG_B>>>(bo, out);
}